// round 4
// baseline (speedup 1.0000x reference)
#include <cuda_runtime.h>
#include <math.h>
#include <stdint.h>

#define H    1024
#define V    32000
#define B    32
#define T    64
#define G3H  3072
#define BM   128
#define NMT  (V / BM)          // 250 logits m-tiles
#define KSP  4                 // GRU K-split
#define OUT_LOGP 65536000LL    // B*T*V

typedef unsigned long long ull;

// ---------------- device scratch (no allocations allowed) ----------------
__device__ float g_h[2][H * B];           // hidden, transposed [k][b], double buffer
__device__ float g_Cb[KSP][B][2 * G3H];   // GRU gate partials [ksplit][b][m]
__device__ float g_pval[B][NMT];          // per-m-tile argmax partials
__device__ int   g_pidx[B][NMT];
__device__ float g_rowmax[B * T];         // max logit per (b,t) for log_softmax
__device__ int   g_tok[B];

// ---------------- packed fp32x2 helpers ----------------
__device__ __forceinline__ ull splat2(float x) {
    ull r; asm("mov.b64 %0, {%1, %1};" : "=l"(r) : "f"(x)); return r;
}
__device__ __forceinline__ void fma2(ull& d, ull a, ull b) {
    asm("fma.rn.f32x2 %0, %1, %2, %0;" : "+l"(d) : "l"(a), "l"(b));
}
__device__ __forceinline__ float2 unpk(ull v) {
    float2 f; asm("mov.b64 {%0, %1}, %2;" : "=f"(f.x), "=f"(f.y) : "l"(v)); return f;
}

// =====================================================================
// init: h0 = encoder_hidden[0] transposed; tok = SOS(0)
// =====================================================================
__global__ void init_k(const float* __restrict__ enc_h)
{
    int b = blockIdx.x, k = threadIdx.x;          // 32 x 1024
    g_h[0][k * B + b] = enc_h[b * H + k];
    if (b == 0 && k < B) g_tok[k] = 0;
}

// =====================================================================
// GRU gates GEMM, K-split: C[m][b] = sum_{k in split} W[m][k] * X[k][b]
//   blockIdx.x < 24 : W_ih rows, X = relu(emb[tok[b]])   (tok = fused argmax
//                     over previous step's logits partials)
//   blockIdx.x >= 24: W_hh rows, X = h_old
// tile BM=128 m x 32 b, K-tile 32, 8 k-tiles per block; 128 threads;
// per-thread 8m x 4b with packed f32x2 FMA.
// =====================================================================
__global__ void __launch_bounds__(128) gru_gemm(
    const float* __restrict__ Wih, const float* __restrict__ Whh,
    const float* __restrict__ emb, int t)
{
    const int m0 = blockIdx.x * BM;
    const int ks = blockIdx.y;
    const bool ih = (m0 < G3H);
    const float* __restrict__ Wm = ih ? (Wih + (size_t)m0 * H)
                                      : (Whh + (size_t)(m0 - G3H) * H);
    const float* __restrict__ hb = g_h[t & 1];

    __shared__ float As[32][BM + 4];   // [kk][m], pad 132 -> conflict-free STS
    __shared__ float Bs[32][36];       // [kk][b]
    __shared__ int   srow[B];

    const int tid = threadIdx.x;
    const int tm = tid & 15;           // 16 m-groups of 8
    const int tb = tid >> 4;           // 8 b-groups of 4
    const int lr = tid >> 1;           // A loader: row 0..63 (two 64-row halves)
    const int lh = (tid & 1) * 4;      //           k float offset 0 / 4
    const int bk = tid >> 2;           // B loader: k 0..31
    const int bb = (tid & 3) * 8;      //           b 0,8,16,24

    // ---- fused argmax of previous step's logits (ih blocks only) ----
    if (ih) {
        if (t > 0) {
            int b = tid >> 2, li = tid & 3;
            float v = -INFINITY; int idx = 0x7fffffff;
            for (int i = li; i < NMT; i += 4) {
                float pv = g_pval[b][i]; int pi = g_pidx[b][i];
                if (pv > v || (pv == v && pi < idx)) { v = pv; idx = pi; }
            }
            #pragma unroll
            for (int off = 2; off > 0; off >>= 1) {
                float ov = __shfl_down_sync(0xffffffffu, v, off, 4);
                int   oi = __shfl_down_sync(0xffffffffu, idx, off, 4);
                if (ov > v || (ov == v && oi < idx)) { v = ov; idx = oi; }
            }
            if (li == 0) {
                srow[b] = idx * H;
                if (blockIdx.x == 0 && ks == 0) g_rowmax[b * T + (t - 1)] = v;
            }
        } else if (tid < B) {
            srow[tid] = 0;             // SOS token
        }
        __syncthreads();
    }

    const int kbase = ks * (H / KSP);  // 256 k per split

    float4 apre[8];
    float4 bq0, bq1;

    // prologue: prefetch k-tile 0
    {
        const int k0 = kbase;
        #pragma unroll
        for (int rr = 0; rr < 2; rr++)
            #pragma unroll
            for (int i = 0; i < 4; i++)
                apre[rr * 4 + i] = *(const float4*)(Wm + (size_t)(rr * 64 + lr) * H + k0 + lh + 8 * i);
        if (ih) {
            int kg = k0 + bk;
            bq0.x = fmaxf(emb[(size_t)srow[bb + 0] + kg], 0.f);
            bq0.y = fmaxf(emb[(size_t)srow[bb + 1] + kg], 0.f);
            bq0.z = fmaxf(emb[(size_t)srow[bb + 2] + kg], 0.f);
            bq0.w = fmaxf(emb[(size_t)srow[bb + 3] + kg], 0.f);
            bq1.x = fmaxf(emb[(size_t)srow[bb + 4] + kg], 0.f);
            bq1.y = fmaxf(emb[(size_t)srow[bb + 5] + kg], 0.f);
            bq1.z = fmaxf(emb[(size_t)srow[bb + 6] + kg], 0.f);
            bq1.w = fmaxf(emb[(size_t)srow[bb + 7] + kg], 0.f);
        } else {
            bq0 = *(const float4*)(hb + (k0 + bk) * B + bb);
            bq1 = *(const float4*)(hb + (k0 + bk) * B + bb + 4);
        }
    }

    ull acc[4][4];
    #pragma unroll
    for (int p = 0; p < 4; p++)
        #pragma unroll
        for (int j = 0; j < 4; j++) acc[p][j] = 0ull;

    for (int kt = 0; kt < 8; kt++) {
        // stage to smem
        #pragma unroll
        for (int rr = 0; rr < 2; rr++)
            #pragma unroll
            for (int i = 0; i < 4; i++) {
                float4 v = apre[rr * 4 + i];
                int kk = lh + 8 * i;
                int m = rr * 64 + lr;
                As[kk + 0][m] = v.x; As[kk + 1][m] = v.y;
                As[kk + 2][m] = v.z; As[kk + 3][m] = v.w;
            }
        *(float4*)&Bs[bk][bb]     = bq0;
        *(float4*)&Bs[bk][bb + 4] = bq1;
        __syncthreads();

        // prefetch next k-tile
        if (kt + 1 < 8) {
            const int k0 = kbase + (kt + 1) * 32;
            #pragma unroll
            for (int rr = 0; rr < 2; rr++)
                #pragma unroll
                for (int i = 0; i < 4; i++)
                    apre[rr * 4 + i] = *(const float4*)(Wm + (size_t)(rr * 64 + lr) * H + k0 + lh + 8 * i);
            if (ih) {
                int kg = k0 + bk;
                bq0.x = fmaxf(emb[(size_t)srow[bb + 0] + kg], 0.f);
                bq0.y = fmaxf(emb[(size_t)srow[bb + 1] + kg], 0.f);
                bq0.z = fmaxf(emb[(size_t)srow[bb + 2] + kg], 0.f);
                bq0.w = fmaxf(emb[(size_t)srow[bb + 3] + kg], 0.f);
                bq1.x = fmaxf(emb[(size_t)srow[bb + 4] + kg], 0.f);
                bq1.y = fmaxf(emb[(size_t)srow[bb + 5] + kg], 0.f);
                bq1.z = fmaxf(emb[(size_t)srow[bb + 6] + kg], 0.f);
                bq1.w = fmaxf(emb[(size_t)srow[bb + 7] + kg], 0.f);
            } else {
                bq0 = *(const float4*)(hb + (k0 + bk) * B + bb);
                bq1 = *(const float4*)(hb + (k0 + bk) * B + bb + 4);
            }
        }

        #pragma unroll 16
        for (int kk = 0; kk < 32; kk++) {
            const ull* ap = (const ull*)&As[kk][8 * tm];
            ull a0 = ap[0], a1 = ap[1], a2 = ap[2], a3 = ap[3];
            float4 bv = *(const float4*)&Bs[kk][4 * tb];
            ull s;
            s = splat2(bv.x); fma2(acc[0][0], a0, s); fma2(acc[1][0], a1, s); fma2(acc[2][0], a2, s); fma2(acc[3][0], a3, s);
            s = splat2(bv.y); fma2(acc[0][1], a0, s); fma2(acc[1][1], a1, s); fma2(acc[2][1], a2, s); fma2(acc[3][1], a3, s);
            s = splat2(bv.z); fma2(acc[0][2], a0, s); fma2(acc[1][2], a1, s); fma2(acc[2][2], a2, s); fma2(acc[3][2], a3, s);
            s = splat2(bv.w); fma2(acc[0][3], a0, s); fma2(acc[1][3], a1, s); fma2(acc[2][3], a2, s); fma2(acc[3][3], a3, s);
        }
        __syncthreads();
    }

    #pragma unroll
    for (int j = 0; j < 4; j++) {
        int b = 4 * tb + j;
        float2 p0 = unpk(acc[0][j]), p1 = unpk(acc[1][j]);
        float2 p2 = unpk(acc[2][j]), p3 = unpk(acc[3][j]);
        float4 o0 = make_float4(p0.x, p0.y, p1.x, p1.y);
        float4 o1 = make_float4(p2.x, p2.y, p3.x, p3.y);
        *(float4*)&g_Cb[ks][b][m0 + 8 * tm]     = o0;
        *(float4*)&g_Cb[ks][b][m0 + 8 * tm + 4] = o1;
    }
}

// =====================================================================
// GRU cell: sum K-split partials + biases -> h_new (buffer (t+1)&1)
// =====================================================================
__global__ void __launch_bounds__(256) gru_cell(
    const float* __restrict__ bih, const float* __restrict__ bhh, int t)
{
    int gid = blockIdx.x * 256 + threadIdx.x;      // 32768
    int b = gid >> 10;
    int j = gid & 1023;
    float gir = 0.f, giz = 0.f, gin = 0.f, ghr = 0.f, ghz = 0.f, ghn = 0.f;
    #pragma unroll
    for (int s = 0; s < KSP; s++) {
        const float* C = g_Cb[s][b];
        gir += C[j];           giz += C[H + j];       gin += C[2 * H + j];
        ghr += C[G3H + j];     ghz += C[G3H + H + j]; ghn += C[G3H + 2 * H + j];
    }
    float r = 1.f / (1.f + expf(-(gir + bih[j]       + ghr + bhh[j])));
    float z = 1.f / (1.f + expf(-(giz + bih[H + j]   + ghz + bhh[H + j])));
    float n = tanhf(gin + bih[2 * H + j] + r * (ghn + bhh[2 * H + j]));
    float hold = g_h[t & 1][j * B + b];
    g_h[(t + 1) & 1][j * B + b] = (1.f - z) * n + z * hold;
}

// =====================================================================
// Logits GEMM + bias + store + per-tile argmax partials
// tile BM=128 m x 32 b, K=1024 (32 tiles), 128 threads, 8m x 4b / thread
// =====================================================================
__global__ void __launch_bounds__(128) logits_gemm(
    const float* __restrict__ Wout, const float* __restrict__ bout,
    float* __restrict__ out, int t)
{
    const int mt = blockIdx.x;
    const int m0 = mt * BM;
    const float* __restrict__ Wm = Wout + (size_t)m0 * H;
    const float* __restrict__ hb = g_h[(t + 1) & 1];

    __shared__ float As[32][BM + 4];
    __shared__ float Bs[32][36];

    const int tid = threadIdx.x;
    const int tm = tid & 15;
    const int tb = tid >> 4;
    const int lr = tid >> 1;
    const int lh = (tid & 1) * 4;
    const int bk = tid >> 2;
    const int bb = (tid & 3) * 8;

    float4 apre[8];
    float4 bq0, bq1;
    {
        #pragma unroll
        for (int rr = 0; rr < 2; rr++)
            #pragma unroll
            for (int i = 0; i < 4; i++)
                apre[rr * 4 + i] = *(const float4*)(Wm + (size_t)(rr * 64 + lr) * H + lh + 8 * i);
        bq0 = *(const float4*)(hb + bk * B + bb);
        bq1 = *(const float4*)(hb + bk * B + bb + 4);
    }

    ull acc[4][4];
    #pragma unroll
    for (int p = 0; p < 4; p++)
        #pragma unroll
        for (int j = 0; j < 4; j++) acc[p][j] = 0ull;

    for (int kt = 0; kt < 32; kt++) {
        #pragma unroll
        for (int rr = 0; rr < 2; rr++)
            #pragma unroll
            for (int i = 0; i < 4; i++) {
                float4 v = apre[rr * 4 + i];
                int kk = lh + 8 * i;
                int m = rr * 64 + lr;
                As[kk + 0][m] = v.x; As[kk + 1][m] = v.y;
                As[kk + 2][m] = v.z; As[kk + 3][m] = v.w;
            }
        *(float4*)&Bs[bk][bb]     = bq0;
        *(float4*)&Bs[bk][bb + 4] = bq1;
        __syncthreads();

        if (kt + 1 < 32) {
            const int k0 = (kt + 1) * 32;
            #pragma unroll
            for (int rr = 0; rr < 2; rr++)
                #pragma unroll
                for (int i = 0; i < 4; i++)
                    apre[rr * 4 + i] = *(const float4*)(Wm + (size_t)(rr * 64 + lr) * H + k0 + lh + 8 * i);
            bq0 = *(const float4*)(hb + (k0 + bk) * B + bb);
            bq1 = *(const float4*)(hb + (k0 + bk) * B + bb + 4);
        }

        #pragma unroll 16
        for (int kk = 0; kk < 32; kk++) {
            const ull* ap = (const ull*)&As[kk][8 * tm];
            ull a0 = ap[0], a1 = ap[1], a2 = ap[2], a3 = ap[3];
            float4 bv = *(const float4*)&Bs[kk][4 * tb];
            ull s;
            s = splat2(bv.x); fma2(acc[0][0], a0, s); fma2(acc[1][0], a1, s); fma2(acc[2][0], a2, s); fma2(acc[3][0], a3, s);
            s = splat2(bv.y); fma2(acc[0][1], a0, s); fma2(acc[1][1], a1, s); fma2(acc[2][1], a2, s); fma2(acc[3][1], a3, s);
            s = splat2(bv.z); fma2(acc[0][2], a0, s); fma2(acc[1][2], a1, s); fma2(acc[2][2], a2, s); fma2(acc[3][2], a3, s);
            s = splat2(bv.w); fma2(acc[0][3], a0, s); fma2(acc[1][3], a1, s); fma2(acc[2][3], a2, s); fma2(acc[3][3], a3, s);
        }
        __syncthreads();
    }

    float4 bias0 = *(const float4*)&bout[m0 + 8 * tm];
    float4 bias1 = *(const float4*)&bout[m0 + 8 * tm + 4];
    #pragma unroll
    for (int j = 0; j < 4; j++) {
        int b = 4 * tb + j;
        float2 p0 = unpk(acc[0][j]), p1 = unpk(acc[1][j]);
        float2 p2 = unpk(acc[2][j]), p3 = unpk(acc[3][j]);
        float4 o0 = make_float4(p0.x + bias0.x, p0.y + bias0.y, p1.x + bias0.z, p1.y + bias0.w);
        float4 o1 = make_float4(p2.x + bias1.x, p2.y + bias1.y, p3.x + bias1.z, p3.y + bias1.w);
        float* orow = out + ((size_t)b * T + t) * V + m0 + 8 * tm;
        *(float4*)orow       = o0;
        *(float4*)(orow + 4) = o1;

        // thread-local argmax over the 8 m's (first-max tie rule)
        float bv = o0.x; int bi = 0;
        if (o0.y > bv) { bv = o0.y; bi = 1; }
        if (o0.z > bv) { bv = o0.z; bi = 2; }
        if (o0.w > bv) { bv = o0.w; bi = 3; }
        if (o1.x > bv) { bv = o1.x; bi = 4; }
        if (o1.y > bv) { bv = o1.y; bi = 5; }
        if (o1.z > bv) { bv = o1.z; bi = 6; }
        if (o1.w > bv) { bv = o1.w; bi = 7; }
        int gidx = m0 + 8 * tm + bi;
        // reduce across the 16 tm-lanes (same b in each 16-lane segment)
        #pragma unroll
        for (int off = 8; off > 0; off >>= 1) {
            float ov = __shfl_down_sync(0xffffffffu, bv, off, 16);
            int   oi = __shfl_down_sync(0xffffffffu, gidx, off, 16);
            if (ov > bv || (ov == bv && oi < gidx)) { bv = ov; gidx = oi; }
        }
        if (tm == 0) {
            g_pval[b][mt] = bv;
            g_pidx[b][mt] = gidx;
        }
    }
}

// =====================================================================
// final argmax (only for t = T-1 rowmax; token unused afterwards)
// =====================================================================
__global__ void __launch_bounds__(1024) argmax_last(int t)
{
    int b = threadIdx.x >> 5;
    int lane = threadIdx.x & 31;
    float v = -INFINITY;
    int idx = 0x7fffffff;
    for (int i = lane; i < NMT; i += 32) {
        float pv = g_pval[b][i];
        int   pi = g_pidx[b][i];
        if (pv > v || (pv == v && pi < idx)) { v = pv; idx = pi; }
    }
    #pragma unroll
    for (int off = 16; off > 0; off >>= 1) {
        float ov = __shfl_down_sync(0xffffffffu, v, off);
        int   oi = __shfl_down_sync(0xffffffffu, idx, off);
        if (ov > v || (ov == v && oi < idx)) { v = ov; idx = oi; }
    }
    if (lane == 0) {
        g_tok[b] = idx;
        g_rowmax[b * T + t] = v;
    }
}

// =====================================================================
// deferred log_softmax, in-place, one block per (b,t) row, vectorized
// =====================================================================
__global__ void __launch_bounds__(256) lsm_k(float* __restrict__ out)
{
    __shared__ float red[256];
    int r = blockIdx.x;
    float4* row4 = (float4*)(out + (size_t)r * V);
    float mx = g_rowmax[r];
    float s = 0.f;
    for (int i = threadIdx.x; i < V / 4; i += 256) {
        float4 v = row4[i];
        s += expf(v.x - mx) + expf(v.y - mx) + expf(v.z - mx) + expf(v.w - mx);
    }
    red[threadIdx.x] = s;
    __syncthreads();
    for (int off = 128; off > 0; off >>= 1) {
        if (threadIdx.x < off) red[threadIdx.x] += red[threadIdx.x + off];
        __syncthreads();
    }
    float c = mx + logf(red[0]);
    for (int i = threadIdx.x; i < V / 4; i += 256) {
        float4 v = row4[i];
        v.x -= c; v.y -= c; v.z -= c; v.w -= c;
        row4[i] = v;
    }
}

// =====================================================================
// copy final hidden (buffer 0 after 64 steps) to output tail
// =====================================================================
__global__ void copy_h(float* __restrict__ dst)
{
    int b = blockIdx.x, k = threadIdx.x;
    dst[b * H + k] = g_h[0][k * B + b];
}

// =====================================================================
extern "C" void kernel_launch(void* const* d_in, const int* in_sizes, int n_in,
                              void* d_out, int out_size)
{
    const float* enc_h = (const float*)d_in[1];
    const float* emb   = (const float*)d_in[2];
    const float* Wih   = (const float*)d_in[3];
    const float* Whh   = (const float*)d_in[4];
    const float* bih   = (const float*)d_in[5];
    const float* bhh   = (const float*)d_in[6];
    const float* Wout  = (const float*)d_in[7];
    const float* bout  = (const float*)d_in[8];
    float* out = (float*)d_out;

    init_k<<<B, H>>>(enc_h);
    for (int t = 0; t < T; t++) {
        gru_gemm<<<dim3(48, KSP), 128>>>(Wih, Whh, emb, t);   // fused argmax(t-1)
        gru_cell<<<128, 256>>>(bih, bhh, t);
        logits_gemm<<<NMT, 128>>>(Wout, bout, out, t);
    }
    argmax_last<<<1, 1024>>>(T - 1);
    lsm_k<<<B * T, 256>>>(out);
    if ((long long)out_size >= OUT_LOGP + (long long)B * H)
        copy_h<<<B, H>>>(out + OUT_LOGP);
}

// round 7
// speedup vs baseline: 2.4040x; 2.4040x over previous
#include <cuda_runtime.h>
#include <math.h>
#include <stdint.h>

#define H    1024
#define V    32000
#define B    32
#define T    64
#define G3H  3072
#define BM   128
#define NMT  (V / BM)          // 250 logits m-tiles
#define KSP  4                 // GRU K-split
#define APITCH 162             // As row pitch (floats): 162 mod 32 == 2 -> conflict-free STS
#define BPITCH 36
#define OUT_LOGP 65536000LL    // B*T*V

typedef unsigned long long ull;

// ---------------- device scratch (no allocations allowed) ----------------
__device__ float g_h[2][H * B];           // hidden, transposed [k][b], double buffer
__device__ float g_Cb[KSP][B][2 * G3H];   // GRU gate partials [ksplit][b][m]
__device__ float g_pval[B][NMT];          // per-m-tile argmax partials
__device__ int   g_pidx[B][NMT];
__device__ float g_rowmax[B * T];         // max logit per (b,t) for log_softmax
__device__ int   g_tok[B];

// ---------------- packed fp32x2 helpers ----------------
__device__ __forceinline__ ull splat2(float x) {
    ull r; asm("mov.b64 %0, {%1, %1};" : "=l"(r) : "f"(x)); return r;
}
__device__ __forceinline__ void fma2(ull& d, ull a, ull b) {
    asm("fma.rn.f32x2 %0, %1, %2, %0;" : "+l"(d) : "l"(a), "l"(b));
}
__device__ __forceinline__ float2 unpk(ull v) {
    float2 f; asm("mov.b64 {%0, %1}, %2;" : "=f"(f.x), "=f"(f.y) : "l"(v)); return f;
}

// map local m-row r (0..127) to As column: group (r>>3) stride 10, elem r&7
__device__ __forceinline__ int acol(int r) { return (r >> 3) * 10 + (r & 7); }

// =====================================================================
// init: h0 = encoder_hidden[0] transposed; tok = SOS(0)
// =====================================================================
__global__ void init_k(const float* __restrict__ enc_h)
{
    int b = blockIdx.x, k = threadIdx.x;          // 32 x 1024
    g_h[0][k * B + b] = enc_h[b * H + k];
    if (b == 0 && k < B) g_tok[k] = 0;
}

// =====================================================================
// core tile compute: 128 threads, BM=128 x 32b, k-tile 32
// thread (tm = tid&15, tb = tid>>4): microtile 8m x 4b, packed f32x2
// A loader: lr = tid>>2 (row 0..31, 4 passes), lc = tid&3 (k quads)
// =====================================================================

// =====================================================================
// GRU gates GEMM, K-split.
//   blockIdx.x < 24 : W_ih rows, X = relu(emb[tok[b]]) (fused argmax t-1)
//   blockIdx.x >= 24: W_hh rows, X = h_old
// =====================================================================
__global__ void __launch_bounds__(128) gru_gemm(
    const float* __restrict__ Wih, const float* __restrict__ Whh,
    const float* __restrict__ emb, int t)
{
    const int m0 = blockIdx.x * BM;
    const int ks = blockIdx.y;
    const bool ih = (m0 < G3H);
    const float* __restrict__ Wm = ih ? (Wih + (size_t)m0 * H)
                                      : (Whh + (size_t)(m0 - G3H) * H);
    const float* __restrict__ hb = g_h[t & 1];

    __shared__ float As[32][APITCH];
    __shared__ float Bs[32][BPITCH];
    __shared__ int   srow[B];

    const int tid = threadIdx.x;
    const int tm = tid & 15;
    const int tb = tid >> 4;
    const int lr = tid >> 2;           // loader row 0..31 (+32*pass)
    const int lc = tid & 3;            // loader k quad
    const int bk = tid >> 2;           // B loader k 0..31
    const int bb = (tid & 3) * 8;      // B loader b base

    // ---- fused argmax of previous step's logits (ih blocks only) ----
    if (ih) {
        if (t > 0) {
            int b = tid >> 2, li = tid & 3;
            float v = -INFINITY; int idx = 0x7fffffff;
            for (int i = li; i < NMT; i += 4) {
                float pv = g_pval[b][i]; int pi = g_pidx[b][i];
                if (pv > v || (pv == v && pi < idx)) { v = pv; idx = pi; }
            }
            #pragma unroll
            for (int off = 2; off > 0; off >>= 1) {
                float ov = __shfl_down_sync(0xffffffffu, v, off, 4);
                int   oi = __shfl_down_sync(0xffffffffu, idx, off, 4);
                if (ov > v || (ov == v && oi < idx)) { v = ov; idx = oi; }
            }
            if (li == 0) {
                srow[b] = idx * H;
                if (blockIdx.x == 0 && ks == 0) g_rowmax[b * T + (t - 1)] = v;
            }
        } else if (tid < B) {
            srow[tid] = 0;             // SOS token
        }
        __syncthreads();
    }

    const int kbase = ks * (H / KSP);  // 256 k per split

    float4 apre[8];                    // 4 passes x 2 float4
    float4 bq0, bq1;

    // prologue: prefetch k-tile 0
    {
        const int k0 = kbase;
        #pragma unroll
        for (int p = 0; p < 4; p++) {
            const float* wr = Wm + (size_t)(p * 32 + lr) * H + k0;
            apre[p * 2 + 0] = *(const float4*)(wr + 4 * lc);
            apre[p * 2 + 1] = *(const float4*)(wr + 16 + 4 * lc);
        }
        if (ih) {
            int kg = k0 + bk;
            bq0.x = fmaxf(emb[(size_t)srow[bb + 0] + kg], 0.f);
            bq0.y = fmaxf(emb[(size_t)srow[bb + 1] + kg], 0.f);
            bq0.z = fmaxf(emb[(size_t)srow[bb + 2] + kg], 0.f);
            bq0.w = fmaxf(emb[(size_t)srow[bb + 3] + kg], 0.f);
            bq1.x = fmaxf(emb[(size_t)srow[bb + 4] + kg], 0.f);
            bq1.y = fmaxf(emb[(size_t)srow[bb + 5] + kg], 0.f);
            bq1.z = fmaxf(emb[(size_t)srow[bb + 6] + kg], 0.f);
            bq1.w = fmaxf(emb[(size_t)srow[bb + 7] + kg], 0.f);
        } else {
            bq0 = *(const float4*)(hb + (k0 + bk) * B + bb);
            bq1 = *(const float4*)(hb + (k0 + bk) * B + bb + 4);
        }
    }

    ull acc[4][4];
    #pragma unroll
    for (int p = 0; p < 4; p++)
        #pragma unroll
        for (int j = 0; j < 4; j++) acc[p][j] = 0ull;

    for (int kt = 0; kt < 8; kt++) {
        // stage to smem (scalar STS, conflict-free by APITCH=162 construction)
        #pragma unroll
        for (int p = 0; p < 4; p++) {
            int col = acol(p * 32 + lr);
            float4 v0 = apre[p * 2 + 0];
            float4 v1 = apre[p * 2 + 1];
            int ka = 4 * lc, kb2 = 16 + 4 * lc;
            As[ka + 0][col] = v0.x; As[ka + 1][col] = v0.y;
            As[ka + 2][col] = v0.z; As[ka + 3][col] = v0.w;
            As[kb2 + 0][col] = v1.x; As[kb2 + 1][col] = v1.y;
            As[kb2 + 2][col] = v1.z; As[kb2 + 3][col] = v1.w;
        }
        *(float4*)&Bs[bk][bb]     = bq0;
        *(float4*)&Bs[bk][bb + 4] = bq1;
        __syncthreads();

        // prefetch next k-tile
        if (kt + 1 < 8) {
            const int k0 = kbase + (kt + 1) * 32;
            #pragma unroll
            for (int p = 0; p < 4; p++) {
                const float* wr = Wm + (size_t)(p * 32 + lr) * H + k0;
                apre[p * 2 + 0] = *(const float4*)(wr + 4 * lc);
                apre[p * 2 + 1] = *(const float4*)(wr + 16 + 4 * lc);
            }
            if (ih) {
                int kg = k0 + bk;
                bq0.x = fmaxf(emb[(size_t)srow[bb + 0] + kg], 0.f);
                bq0.y = fmaxf(emb[(size_t)srow[bb + 1] + kg], 0.f);
                bq0.z = fmaxf(emb[(size_t)srow[bb + 2] + kg], 0.f);
                bq0.w = fmaxf(emb[(size_t)srow[bb + 3] + kg], 0.f);
                bq1.x = fmaxf(emb[(size_t)srow[bb + 4] + kg], 0.f);
                bq1.y = fmaxf(emb[(size_t)srow[bb + 5] + kg], 0.f);
                bq1.z = fmaxf(emb[(size_t)srow[bb + 6] + kg], 0.f);
                bq1.w = fmaxf(emb[(size_t)srow[bb + 7] + kg], 0.f);
            } else {
                bq0 = *(const float4*)(hb + (k0 + bk) * B + bb);
                bq1 = *(const float4*)(hb + (k0 + bk) * B + bb + 4);
            }
        }

        #pragma unroll 16
        for (int kk = 0; kk < 32; kk++) {
            const float* ab = &As[kk][10 * tm];
            ull a0 = *(const ull*)(ab + 0);
            ull a1 = *(const ull*)(ab + 2);
            ull a2 = *(const ull*)(ab + 4);
            ull a3 = *(const ull*)(ab + 6);
            float4 bv = *(const float4*)&Bs[kk][4 * tb];
            ull s;
            s = splat2(bv.x); fma2(acc[0][0], a0, s); fma2(acc[1][0], a1, s); fma2(acc[2][0], a2, s); fma2(acc[3][0], a3, s);
            s = splat2(bv.y); fma2(acc[0][1], a0, s); fma2(acc[1][1], a1, s); fma2(acc[2][1], a2, s); fma2(acc[3][1], a3, s);
            s = splat2(bv.z); fma2(acc[0][2], a0, s); fma2(acc[1][2], a1, s); fma2(acc[2][2], a2, s); fma2(acc[3][2], a3, s);
            s = splat2(bv.w); fma2(acc[0][3], a0, s); fma2(acc[1][3], a1, s); fma2(acc[2][3], a2, s); fma2(acc[3][3], a3, s);
        }
        __syncthreads();
    }

    #pragma unroll
    for (int j = 0; j < 4; j++) {
        int b = 4 * tb + j;
        float2 p0 = unpk(acc[0][j]), p1 = unpk(acc[1][j]);
        float2 p2 = unpk(acc[2][j]), p3 = unpk(acc[3][j]);
        float4 o0 = make_float4(p0.x, p0.y, p1.x, p1.y);
        float4 o1 = make_float4(p2.x, p2.y, p3.x, p3.y);
        *(float4*)&g_Cb[ks][b][m0 + 8 * tm]     = o0;
        *(float4*)&g_Cb[ks][b][m0 + 8 * tm + 4] = o1;
    }
}

// =====================================================================
// GRU cell: sum K-split partials + biases -> h_new (buffer (t+1)&1)
// =====================================================================
__global__ void __launch_bounds__(256) gru_cell(
    const float* __restrict__ bih, const float* __restrict__ bhh, int t)
{
    int gid = blockIdx.x * 256 + threadIdx.x;      // 32768
    int b = gid >> 10;
    int j = gid & 1023;
    float gir = 0.f, giz = 0.f, gin = 0.f, ghr = 0.f, ghz = 0.f, ghn = 0.f;
    #pragma unroll
    for (int s = 0; s < KSP; s++) {
        const float* C = g_Cb[s][b];
        gir += C[j];           giz += C[H + j];       gin += C[2 * H + j];
        ghr += C[G3H + j];     ghz += C[G3H + H + j]; ghn += C[G3H + 2 * H + j];
    }
    float r = 1.f / (1.f + expf(-(gir + bih[j]       + ghr + bhh[j])));
    float z = 1.f / (1.f + expf(-(giz + bih[H + j]   + ghz + bhh[H + j])));
    float n = tanhf(gin + bih[2 * H + j] + r * (ghn + bhh[2 * H + j]));
    float hold = g_h[t & 1][j * B + b];
    g_h[(t + 1) & 1][j * B + b] = (1.f - z) * n + z * hold;
}

// =====================================================================
// Logits GEMM + bias + store + per-tile argmax partials
// =====================================================================
__global__ void __launch_bounds__(128) logits_gemm(
    const float* __restrict__ Wout, const float* __restrict__ bout,
    float* __restrict__ out, int t)
{
    const int mt = blockIdx.x;
    const int m0 = mt * BM;
    const float* __restrict__ Wm = Wout + (size_t)m0 * H;
    const float* __restrict__ hb = g_h[(t + 1) & 1];

    __shared__ float As[32][APITCH];
    __shared__ float Bs[32][BPITCH];

    const int tid = threadIdx.x;
    const int tm = tid & 15;
    const int tb = tid >> 4;
    const int lr = tid >> 2;
    const int lc = tid & 3;
    const int bk = tid >> 2;
    const int bb = (tid & 3) * 8;

    float4 apre[8];
    float4 bq0, bq1;
    {
        #pragma unroll
        for (int p = 0; p < 4; p++) {
            const float* wr = Wm + (size_t)(p * 32 + lr) * H;
            apre[p * 2 + 0] = *(const float4*)(wr + 4 * lc);
            apre[p * 2 + 1] = *(const float4*)(wr + 16 + 4 * lc);
        }
        bq0 = *(const float4*)(hb + bk * B + bb);
        bq1 = *(const float4*)(hb + bk * B + bb + 4);
    }

    ull acc[4][4];
    #pragma unroll
    for (int p = 0; p < 4; p++)
        #pragma unroll
        for (int j = 0; j < 4; j++) acc[p][j] = 0ull;

    for (int kt = 0; kt < 32; kt++) {
        #pragma unroll
        for (int p = 0; p < 4; p++) {
            int col = acol(p * 32 + lr);
            float4 v0 = apre[p * 2 + 0];
            float4 v1 = apre[p * 2 + 1];
            int ka = 4 * lc, kb2 = 16 + 4 * lc;
            As[ka + 0][col] = v0.x; As[ka + 1][col] = v0.y;
            As[ka + 2][col] = v0.z; As[ka + 3][col] = v0.w;
            As[kb2 + 0][col] = v1.x; As[kb2 + 1][col] = v1.y;
            As[kb2 + 2][col] = v1.z; As[kb2 + 3][col] = v1.w;
        }
        *(float4*)&Bs[bk][bb]     = bq0;
        *(float4*)&Bs[bk][bb + 4] = bq1;
        __syncthreads();

        if (kt + 1 < 32) {
            const int k0 = (kt + 1) * 32;
            #pragma unroll
            for (int p = 0; p < 4; p++) {
                const float* wr = Wm + (size_t)(p * 32 + lr) * H + k0;
                apre[p * 2 + 0] = *(const float4*)(wr + 4 * lc);
                apre[p * 2 + 1] = *(const float4*)(wr + 16 + 4 * lc);
            }
            bq0 = *(const float4*)(hb + (k0 + bk) * B + bb);
            bq1 = *(const float4*)(hb + (k0 + bk) * B + bb + 4);
        }

        #pragma unroll 16
        for (int kk = 0; kk < 32; kk++) {
            const float* ab = &As[kk][10 * tm];
            ull a0 = *(const ull*)(ab + 0);
            ull a1 = *(const ull*)(ab + 2);
            ull a2 = *(const ull*)(ab + 4);
            ull a3 = *(const ull*)(ab + 6);
            float4 bv = *(const float4*)&Bs[kk][4 * tb];
            ull s;
            s = splat2(bv.x); fma2(acc[0][0], a0, s); fma2(acc[1][0], a1, s); fma2(acc[2][0], a2, s); fma2(acc[3][0], a3, s);
            s = splat2(bv.y); fma2(acc[0][1], a0, s); fma2(acc[1][1], a1, s); fma2(acc[2][1], a2, s); fma2(acc[3][1], a3, s);
            s = splat2(bv.z); fma2(acc[0][2], a0, s); fma2(acc[1][2], a1, s); fma2(acc[2][2], a2, s); fma2(acc[3][2], a3, s);
            s = splat2(bv.w); fma2(acc[0][3], a0, s); fma2(acc[1][3], a1, s); fma2(acc[2][3], a2, s); fma2(acc[3][3], a3, s);
        }
        __syncthreads();
    }

    float4 bias0 = *(const float4*)&bout[m0 + 8 * tm];
    float4 bias1 = *(const float4*)&bout[m0 + 8 * tm + 4];
    #pragma unroll
    for (int j = 0; j < 4; j++) {
        int b = 4 * tb + j;
        float2 p0 = unpk(acc[0][j]), p1 = unpk(acc[1][j]);
        float2 p2 = unpk(acc[2][j]), p3 = unpk(acc[3][j]);
        float4 o0 = make_float4(p0.x + bias0.x, p0.y + bias0.y, p1.x + bias0.z, p1.y + bias0.w);
        float4 o1 = make_float4(p2.x + bias1.x, p2.y + bias1.y, p3.x + bias1.z, p3.y + bias1.w);
        float* orow = out + ((size_t)b * T + t) * V + m0 + 8 * tm;
        *(float4*)orow       = o0;
        *(float4*)(orow + 4) = o1;

        // thread-local argmax over 8 m's (first-max tie rule)
        float bv = o0.x; int bi = 0;
        if (o0.y > bv) { bv = o0.y; bi = 1; }
        if (o0.z > bv) { bv = o0.z; bi = 2; }
        if (o0.w > bv) { bv = o0.w; bi = 3; }
        if (o1.x > bv) { bv = o1.x; bi = 4; }
        if (o1.y > bv) { bv = o1.y; bi = 5; }
        if (o1.z > bv) { bv = o1.z; bi = 6; }
        if (o1.w > bv) { bv = o1.w; bi = 7; }
        int gidx = m0 + 8 * tm + bi;
        #pragma unroll
        for (int off = 8; off > 0; off >>= 1) {
            float ov = __shfl_down_sync(0xffffffffu, bv, off, 16);
            int   oi = __shfl_down_sync(0xffffffffu, gidx, off, 16);
            if (ov > bv || (ov == bv && oi < gidx)) { bv = ov; gidx = oi; }
        }
        if (tm == 0) {
            g_pval[b][mt] = bv;
            g_pidx[b][mt] = gidx;
        }
    }
}

// =====================================================================
// final argmax (for t = T-1 rowmax)
// =====================================================================
__global__ void __launch_bounds__(1024) argmax_last(int t)
{
    int b = threadIdx.x >> 5;
    int lane = threadIdx.x & 31;
    float v = -INFINITY;
    int idx = 0x7fffffff;
    for (int i = lane; i < NMT; i += 32) {
        float pv = g_pval[b][i];
        int   pi = g_pidx[b][i];
        if (pv > v || (pv == v && pi < idx)) { v = pv; idx = pi; }
    }
    #pragma unroll
    for (int off = 16; off > 0; off >>= 1) {
        float ov = __shfl_down_sync(0xffffffffu, v, off);
        int   oi = __shfl_down_sync(0xffffffffu, idx, off);
        if (ov > v || (ov == v && oi < idx)) { v = ov; idx = oi; }
    }
    if (lane == 0) {
        g_tok[b] = idx;
        g_rowmax[b * T + t] = v;
    }
}

// =====================================================================
// deferred log_softmax, in-place, one block per (b,t) row
// =====================================================================
__global__ void __launch_bounds__(256) lsm_k(float* __restrict__ out)
{
    __shared__ float red[256];
    int r = blockIdx.x;
    float4* row4 = (float4*)(out + (size_t)r * V);
    float mx = g_rowmax[r];
    float s = 0.f;
    for (int i = threadIdx.x; i < V / 4; i += 256) {
        float4 v = row4[i];
        s += expf(v.x - mx) + expf(v.y - mx) + expf(v.z - mx) + expf(v.w - mx);
    }
    red[threadIdx.x] = s;
    __syncthreads();
    for (int off = 128; off > 0; off >>= 1) {
        if (threadIdx.x < off) red[threadIdx.x] += red[threadIdx.x + off];
        __syncthreads();
    }
    float c = mx + logf(red[0]);
    for (int i = threadIdx.x; i < V / 4; i += 256) {
        float4 v = row4[i];
        v.x -= c; v.y -= c; v.z -= c; v.w -= c;
        row4[i] = v;
    }
}

// =====================================================================
// copy final hidden (buffer 0 after 64 steps) to output tail
// =====================================================================
__global__ void copy_h(float* __restrict__ dst)
{
    int b = blockIdx.x, k = threadIdx.x;
    dst[b * H + k] = g_h[0][k * B + b];
}

// =====================================================================
extern "C" void kernel_launch(void* const* d_in, const int* in_sizes, int n_in,
                              void* d_out, int out_size)
{
    const float* enc_h = (const float*)d_in[1];
    const float* emb   = (const float*)d_in[2];
    const float* Wih   = (const float*)d_in[3];
    const float* Whh   = (const float*)d_in[4];
    const float* bih   = (const float*)d_in[5];
    const float* bhh   = (const float*)d_in[6];
    const float* Wout  = (const float*)d_in[7];
    const float* bout  = (const float*)d_in[8];
    float* out = (float*)d_out;

    init_k<<<B, H>>>(enc_h);
    for (int t = 0; t < T; t++) {
        gru_gemm<<<dim3(48, KSP), 128>>>(Wih, Whh, emb, t);   // fused argmax(t-1)
        gru_cell<<<128, 256>>>(bih, bhh, t);
        logits_gemm<<<NMT, 128>>>(Wout, bout, out, t);
    }
    argmax_last<<<1, 1024>>>(T - 1);
    lsm_k<<<B * T, 256>>>(out);
    if ((long long)out_size >= OUT_LOGP + (long long)B * H)
        copy_h<<<B, H>>>(out + OUT_LOGP);
}

// round 8
// speedup vs baseline: 2.5230x; 1.0495x over previous
#include <cuda_runtime.h>
#include <math.h>
#include <stdint.h>

#define H    1024
#define V    32000
#define B    32
#define T    64
#define G3H  3072
#define BM   256               // logits m-tile
#define NMT  (V / BM)          // 125 logits m-tiles (single wave on 148 SMs)
#define KSP  4                 // GRU K-split
#define GPITCH 162             // gru As pitch (stride-10 groups, 16 tm lanes)
#define LPITCH 322             // logits As pitch: 322 mod 32 == 2 -> conflict-free STS
#define BPITCH 36
#define OUT_LOGP 65536000LL    // B*T*V

typedef unsigned long long ull;

// ---------------- device scratch (no allocations allowed) ----------------
__device__ float g_h[2][H * B];           // hidden, transposed [k][b], double buffer
__device__ float g_Cb[KSP][B][2 * G3H];   // GRU gate partials [ksplit][b][m]
__device__ float g_pval[B][NMT];          // per-m-tile argmax partials
__device__ int   g_pidx[B][NMT];
__device__ float g_rowmax[B * T];         // max logit per (b,t) for log_softmax
__device__ int   g_tok[B];

// ---------------- packed fp32x2 helpers ----------------
__device__ __forceinline__ ull splat2(float x) {
    ull r; asm("mov.b64 %0, {%1, %1};" : "=l"(r) : "f"(x)); return r;
}
__device__ __forceinline__ void fma2(ull& d, ull a, ull b) {
    asm("fma.rn.f32x2 %0, %1, %2, %0;" : "+l"(d) : "l"(a), "l"(b));
}
__device__ __forceinline__ float2 unpk(ull v) {
    float2 f; asm("mov.b64 {%0, %1}, %2;" : "=f"(f.x), "=f"(f.y) : "l"(v)); return f;
}

// gru: map local m-row r (0..127) to As column: group stride 10
__device__ __forceinline__ int acol(int r) { return (r >> 3) * 10 + (r & 7); }

// =====================================================================
// init: h0 = encoder_hidden[0] transposed; tok = SOS(0)
// =====================================================================
__global__ void init_k(const float* __restrict__ enc_h)
{
    int b = blockIdx.x, k = threadIdx.x;          // 32 x 1024
    g_h[0][k * B + b] = enc_h[b * H + k];
    if (b == 0 && k < B) g_tok[k] = 0;
}

// =====================================================================
// GRU gates GEMM, K-split (unchanged structure from R7).
//   blockIdx.x < 24 : W_ih rows, X = relu(emb[tok[b]]) (fused argmax t-1)
//   blockIdx.x >= 24: W_hh rows, X = h_old
// BM=128 x 32b, k-tile 32, 8 tiles/block; 128 threads; 8m x 4b f32x2
// =====================================================================
__global__ void __launch_bounds__(128) gru_gemm(
    const float* __restrict__ Wih, const float* __restrict__ Whh,
    const float* __restrict__ emb, int t)
{
    const int m0 = blockIdx.x * 128;
    const int ks = blockIdx.y;
    const bool ih = (m0 < G3H);
    const float* __restrict__ Wm = ih ? (Wih + (size_t)m0 * H)
                                      : (Whh + (size_t)(m0 - G3H) * H);
    const float* __restrict__ hb = g_h[t & 1];

    __shared__ float As[32][GPITCH];
    __shared__ float Bs[32][BPITCH];
    __shared__ int   srow[B];

    const int tid = threadIdx.x;
    const int tm = tid & 15;
    const int tb = tid >> 4;
    const int lr = tid >> 2;           // loader row 0..31 (+32*pass)
    const int lc = tid & 3;            // loader k quad
    const int bk = tid >> 2;           // B loader k 0..31
    const int bb = (tid & 3) * 8;      // B loader b base

    // ---- fused argmax of previous step's logits (ih blocks only) ----
    if (ih) {
        if (t > 0) {
            int b = tid >> 2, li = tid & 3;
            float v = -INFINITY; int idx = 0x7fffffff;
            for (int i = li; i < NMT; i += 4) {
                float pv = g_pval[b][i]; int pi = g_pidx[b][i];
                if (pv > v || (pv == v && pi < idx)) { v = pv; idx = pi; }
            }
            #pragma unroll
            for (int off = 2; off > 0; off >>= 1) {
                float ov = __shfl_down_sync(0xffffffffu, v, off, 4);
                int   oi = __shfl_down_sync(0xffffffffu, idx, off, 4);
                if (ov > v || (ov == v && oi < idx)) { v = ov; idx = oi; }
            }
            if (li == 0) {
                srow[b] = idx * H;
                if (blockIdx.x == 0 && ks == 0) g_rowmax[b * T + (t - 1)] = v;
            }
        } else if (tid < B) {
            srow[tid] = 0;             // SOS token
        }
        __syncthreads();
    }

    const int kbase = ks * (H / KSP);  // 256 k per split

    float4 apre[8];                    // 4 passes x 2 float4
    float4 bq0, bq1;

    {
        const int k0 = kbase;
        #pragma unroll
        for (int p = 0; p < 4; p++) {
            const float* wr = Wm + (size_t)(p * 32 + lr) * H + k0;
            apre[p * 2 + 0] = *(const float4*)(wr + 4 * lc);
            apre[p * 2 + 1] = *(const float4*)(wr + 16 + 4 * lc);
        }
        if (ih) {
            int kg = k0 + bk;
            bq0.x = fmaxf(emb[(size_t)srow[bb + 0] + kg], 0.f);
            bq0.y = fmaxf(emb[(size_t)srow[bb + 1] + kg], 0.f);
            bq0.z = fmaxf(emb[(size_t)srow[bb + 2] + kg], 0.f);
            bq0.w = fmaxf(emb[(size_t)srow[bb + 3] + kg], 0.f);
            bq1.x = fmaxf(emb[(size_t)srow[bb + 4] + kg], 0.f);
            bq1.y = fmaxf(emb[(size_t)srow[bb + 5] + kg], 0.f);
            bq1.z = fmaxf(emb[(size_t)srow[bb + 6] + kg], 0.f);
            bq1.w = fmaxf(emb[(size_t)srow[bb + 7] + kg], 0.f);
        } else {
            bq0 = *(const float4*)(hb + (k0 + bk) * B + bb);
            bq1 = *(const float4*)(hb + (k0 + bk) * B + bb + 4);
        }
    }

    ull acc[4][4];
    #pragma unroll
    for (int p = 0; p < 4; p++)
        #pragma unroll
        for (int j = 0; j < 4; j++) acc[p][j] = 0ull;

    for (int kt = 0; kt < 8; kt++) {
        #pragma unroll
        for (int p = 0; p < 4; p++) {
            int col = acol(p * 32 + lr);
            float4 v0 = apre[p * 2 + 0];
            float4 v1 = apre[p * 2 + 1];
            int ka = 4 * lc, kb2 = 16 + 4 * lc;
            As[ka + 0][col] = v0.x; As[ka + 1][col] = v0.y;
            As[ka + 2][col] = v0.z; As[ka + 3][col] = v0.w;
            As[kb2 + 0][col] = v1.x; As[kb2 + 1][col] = v1.y;
            As[kb2 + 2][col] = v1.z; As[kb2 + 3][col] = v1.w;
        }
        *(float4*)&Bs[bk][bb]     = bq0;
        *(float4*)&Bs[bk][bb + 4] = bq1;
        __syncthreads();

        if (kt + 1 < 8) {
            const int k0 = kbase + (kt + 1) * 32;
            #pragma unroll
            for (int p = 0; p < 4; p++) {
                const float* wr = Wm + (size_t)(p * 32 + lr) * H + k0;
                apre[p * 2 + 0] = *(const float4*)(wr + 4 * lc);
                apre[p * 2 + 1] = *(const float4*)(wr + 16 + 4 * lc);
            }
            if (ih) {
                int kg = k0 + bk;
                bq0.x = fmaxf(emb[(size_t)srow[bb + 0] + kg], 0.f);
                bq0.y = fmaxf(emb[(size_t)srow[bb + 1] + kg], 0.f);
                bq0.z = fmaxf(emb[(size_t)srow[bb + 2] + kg], 0.f);
                bq0.w = fmaxf(emb[(size_t)srow[bb + 3] + kg], 0.f);
                bq1.x = fmaxf(emb[(size_t)srow[bb + 4] + kg], 0.f);
                bq1.y = fmaxf(emb[(size_t)srow[bb + 5] + kg], 0.f);
                bq1.z = fmaxf(emb[(size_t)srow[bb + 6] + kg], 0.f);
                bq1.w = fmaxf(emb[(size_t)srow[bb + 7] + kg], 0.f);
            } else {
                bq0 = *(const float4*)(hb + (k0 + bk) * B + bb);
                bq1 = *(const float4*)(hb + (k0 + bk) * B + bb + 4);
            }
        }

        #pragma unroll 16
        for (int kk = 0; kk < 32; kk++) {
            const float* ab = &As[kk][10 * tm];
            ull a0 = *(const ull*)(ab + 0);
            ull a1 = *(const ull*)(ab + 2);
            ull a2 = *(const ull*)(ab + 4);
            ull a3 = *(const ull*)(ab + 6);
            float4 bv = *(const float4*)&Bs[kk][4 * tb];
            ull s;
            s = splat2(bv.x); fma2(acc[0][0], a0, s); fma2(acc[1][0], a1, s); fma2(acc[2][0], a2, s); fma2(acc[3][0], a3, s);
            s = splat2(bv.y); fma2(acc[0][1], a0, s); fma2(acc[1][1], a1, s); fma2(acc[2][1], a2, s); fma2(acc[3][1], a3, s);
            s = splat2(bv.z); fma2(acc[0][2], a0, s); fma2(acc[1][2], a1, s); fma2(acc[2][2], a2, s); fma2(acc[3][2], a3, s);
            s = splat2(bv.w); fma2(acc[0][3], a0, s); fma2(acc[1][3], a1, s); fma2(acc[2][3], a2, s); fma2(acc[3][3], a3, s);
        }
        __syncthreads();
    }

    #pragma unroll
    for (int j = 0; j < 4; j++) {
        int b = 4 * tb + j;
        float2 p0 = unpk(acc[0][j]), p1 = unpk(acc[1][j]);
        float2 p2 = unpk(acc[2][j]), p3 = unpk(acc[3][j]);
        float4 o0 = make_float4(p0.x, p0.y, p1.x, p1.y);
        float4 o1 = make_float4(p2.x, p2.y, p3.x, p3.y);
        *(float4*)&g_Cb[ks][b][m0 + 8 * tm]     = o0;
        *(float4*)&g_Cb[ks][b][m0 + 8 * tm + 4] = o1;
    }
}

// =====================================================================
// GRU cell: sum K-split partials + biases -> h_new (buffer (t+1)&1)
// =====================================================================
__global__ void __launch_bounds__(256) gru_cell(
    const float* __restrict__ bih, const float* __restrict__ bhh, int t)
{
    int gid = blockIdx.x * 256 + threadIdx.x;      // 32768
    int b = gid >> 10;
    int j = gid & 1023;
    float gir = 0.f, giz = 0.f, gin = 0.f, ghr = 0.f, ghz = 0.f, ghn = 0.f;
    #pragma unroll
    for (int s = 0; s < KSP; s++) {
        const float* C = g_Cb[s][b];
        gir += C[j];           giz += C[H + j];       gin += C[2 * H + j];
        ghr += C[G3H + j];     ghz += C[G3H + H + j]; ghn += C[G3H + 2 * H + j];
    }
    float r = 1.f / (1.f + expf(-(gir + bih[j]       + ghr + bhh[j])));
    float z = 1.f / (1.f + expf(-(giz + bih[H + j]   + ghz + bhh[H + j])));
    float n = tanhf(gin + bih[2 * H + j] + r * (ghn + bhh[2 * H + j]));
    float hold = g_h[t & 1][j * B + b];
    g_h[(t + 1) & 1][j * B + b] = (1.f - z) * n + z * hold;
}

// =====================================================================
// Logits GEMM: BM=256, grid=125 (single wave), 128 threads.
// k-tile 16 (64 tiles). Per-thread microtile 16m x 4b (two 8-m groups,
// lanes 16..31 broadcast-read lanes 0..15's A columns -> 1-phase LDS).
// =====================================================================
__global__ void __launch_bounds__(128) logits_gemm(
    const float* __restrict__ Wout, const float* __restrict__ bout,
    float* __restrict__ out, int t)
{
    const int mt = blockIdx.x;
    const int m0 = mt * BM;
    const float* __restrict__ Wm = Wout + (size_t)m0 * H;
    const float* __restrict__ hb = g_h[(t + 1) & 1];

    __shared__ float As[16][LPITCH];   // [kk][col], col = (m>>3)*10 + (m&7)
    __shared__ float Bs[16][BPITCH];

    const int tid = threadIdx.x;
    const int tm = tid & 15;           // m group within half
    const int tb = tid >> 4;           // 8 b-groups of 4
    const int lr = tid >> 2;           // A loader row 0..31 (+32*pass, 8 passes)
    const int lc = tid & 3;            // A loader k quad (16 k per tile)
    const int bk = tid >> 3;           // B loader k 0..15
    const int bb = (tid & 7) * 4;      // B loader b base

    float4 apre[8];                    // 8 passes x 1 float4
    float4 bq;

    {
        #pragma unroll
        for (int p = 0; p < 8; p++)
            apre[p] = *(const float4*)(Wm + (size_t)(p * 32 + lr) * H + 4 * lc);
        bq = *(const float4*)(hb + bk * B + bb);
    }

    ull acc[8][4];
    #pragma unroll
    for (int p = 0; p < 8; p++)
        #pragma unroll
        for (int j = 0; j < 4; j++) acc[p][j] = 0ull;

    for (int kt = 0; kt < 64; kt++) {
        // stage current tile (STS conflict-free: bank = 2*kk + col covers 32)
        #pragma unroll
        for (int p = 0; p < 8; p++) {
            int m = p * 32 + lr;
            int col = (m >> 3) * 10 + (m & 7);
            float4 v = apre[p];
            int ka = 4 * lc;
            As[ka + 0][col] = v.x; As[ka + 1][col] = v.y;
            As[ka + 2][col] = v.z; As[ka + 3][col] = v.w;
        }
        *(float4*)&Bs[bk][bb] = bq;
        __syncthreads();

        // prefetch next tile
        if (kt + 1 < 64) {
            const int k0 = (kt + 1) * 16;
            #pragma unroll
            for (int p = 0; p < 8; p++)
                apre[p] = *(const float4*)(Wm + (size_t)(p * 32 + lr) * H + k0 + 4 * lc);
            bq = *(const float4*)(hb + (k0 + bk) * B + bb);
        }

        #pragma unroll
        for (int kk = 0; kk < 16; kk++) {
            const float* ab = &As[kk][10 * tm];
            ull a0 = *(const ull*)(ab + 0);
            ull a1 = *(const ull*)(ab + 2);
            ull a2 = *(const ull*)(ab + 4);
            ull a3 = *(const ull*)(ab + 6);
            ull a4 = *(const ull*)(ab + 160);
            ull a5 = *(const ull*)(ab + 162);
            ull a6 = *(const ull*)(ab + 164);
            ull a7 = *(const ull*)(ab + 166);
            float4 bv = *(const float4*)&Bs[kk][4 * tb];
            ull s;
            s = splat2(bv.x);
            fma2(acc[0][0], a0, s); fma2(acc[1][0], a1, s); fma2(acc[2][0], a2, s); fma2(acc[3][0], a3, s);
            fma2(acc[4][0], a4, s); fma2(acc[5][0], a5, s); fma2(acc[6][0], a6, s); fma2(acc[7][0], a7, s);
            s = splat2(bv.y);
            fma2(acc[0][1], a0, s); fma2(acc[1][1], a1, s); fma2(acc[2][1], a2, s); fma2(acc[3][1], a3, s);
            fma2(acc[4][1], a4, s); fma2(acc[5][1], a5, s); fma2(acc[6][1], a6, s); fma2(acc[7][1], a7, s);
            s = splat2(bv.z);
            fma2(acc[0][2], a0, s); fma2(acc[1][2], a1, s); fma2(acc[2][2], a2, s); fma2(acc[3][2], a3, s);
            fma2(acc[4][2], a4, s); fma2(acc[5][2], a5, s); fma2(acc[6][2], a6, s); fma2(acc[7][2], a7, s);
            s = splat2(bv.w);
            fma2(acc[0][3], a0, s); fma2(acc[1][3], a1, s); fma2(acc[2][3], a2, s); fma2(acc[3][3], a3, s);
            fma2(acc[4][3], a4, s); fma2(acc[5][3], a5, s); fma2(acc[6][3], a6, s); fma2(acc[7][3], a7, s);
        }
        __syncthreads();
    }

    // epilogue: bias, store, fused per-tile argmax partials
    float4 bias0 = *(const float4*)&bout[m0 + 8 * tm];
    float4 bias1 = *(const float4*)&bout[m0 + 8 * tm + 4];
    float4 bias2 = *(const float4*)&bout[m0 + 128 + 8 * tm];
    float4 bias3 = *(const float4*)&bout[m0 + 128 + 8 * tm + 4];
    #pragma unroll
    for (int j = 0; j < 4; j++) {
        int b = 4 * tb + j;
        float2 q0 = unpk(acc[0][j]), q1 = unpk(acc[1][j]);
        float2 q2 = unpk(acc[2][j]), q3 = unpk(acc[3][j]);
        float2 q4 = unpk(acc[4][j]), q5 = unpk(acc[5][j]);
        float2 q6 = unpk(acc[6][j]), q7 = unpk(acc[7][j]);
        float4 o0 = make_float4(q0.x + bias0.x, q0.y + bias0.y, q1.x + bias0.z, q1.y + bias0.w);
        float4 o1 = make_float4(q2.x + bias1.x, q2.y + bias1.y, q3.x + bias1.z, q3.y + bias1.w);
        float4 o2 = make_float4(q4.x + bias2.x, q4.y + bias2.y, q5.x + bias2.z, q5.y + bias2.w);
        float4 o3 = make_float4(q6.x + bias3.x, q6.y + bias3.y, q7.x + bias3.z, q7.y + bias3.w);
        float* orow = out + ((size_t)b * T + t) * V + m0 + 8 * tm;
        *(float4*)orow         = o0;
        *(float4*)(orow + 4)   = o1;
        *(float4*)(orow + 128) = o2;
        *(float4*)(orow + 132) = o3;

        // thread-local argmax over 16 m's (first-max tie rule: ascending m)
        float bv = o0.x; int bi = 0;
        if (o0.y > bv) { bv = o0.y; bi = 1; }
        if (o0.z > bv) { bv = o0.z; bi = 2; }
        if (o0.w > bv) { bv = o0.w; bi = 3; }
        if (o1.x > bv) { bv = o1.x; bi = 4; }
        if (o1.y > bv) { bv = o1.y; bi = 5; }
        if (o1.z > bv) { bv = o1.z; bi = 6; }
        if (o1.w > bv) { bv = o1.w; bi = 7; }
        if (o2.x > bv) { bv = o2.x; bi = 128; }
        if (o2.y > bv) { bv = o2.y; bi = 129; }
        if (o2.z > bv) { bv = o2.z; bi = 130; }
        if (o2.w > bv) { bv = o2.w; bi = 131; }
        if (o3.x > bv) { bv = o3.x; bi = 132; }
        if (o3.y > bv) { bv = o3.y; bi = 133; }
        if (o3.z > bv) { bv = o3.z; bi = 134; }
        if (o3.w > bv) { bv = o3.w; bi = 135; }
        int gidx = m0 + 8 * tm + bi;
        // reduce across 16 tm-lanes (same b within each 16-lane half)
        #pragma unroll
        for (int off = 8; off > 0; off >>= 1) {
            float ov = __shfl_down_sync(0xffffffffu, bv, off, 16);
            int   oi = __shfl_down_sync(0xffffffffu, gidx, off, 16);
            if (ov > bv || (ov == bv && oi < gidx)) { bv = ov; gidx = oi; }
        }
        if (tm == 0) {
            g_pval[b][mt] = bv;
            g_pidx[b][mt] = gidx;
        }
    }
}

// =====================================================================
// final argmax (for t = T-1 rowmax)
// =====================================================================
__global__ void __launch_bounds__(1024) argmax_last(int t)
{
    int b = threadIdx.x >> 5;
    int lane = threadIdx.x & 31;
    float v = -INFINITY;
    int idx = 0x7fffffff;
    for (int i = lane; i < NMT; i += 32) {
        float pv = g_pval[b][i];
        int   pi = g_pidx[b][i];
        if (pv > v || (pv == v && pi < idx)) { v = pv; idx = pi; }
    }
    #pragma unroll
    for (int off = 16; off > 0; off >>= 1) {
        float ov = __shfl_down_sync(0xffffffffu, v, off);
        int   oi = __shfl_down_sync(0xffffffffu, idx, off);
        if (ov > v || (ov == v && oi < idx)) { v = ov; idx = oi; }
    }
    if (lane == 0) {
        g_tok[b] = idx;
        g_rowmax[b * T + t] = v;
    }
}

// =====================================================================
// deferred log_softmax, in-place, one block per (b,t) row
// =====================================================================
__global__ void __launch_bounds__(256) lsm_k(float* __restrict__ out)
{
    __shared__ float red[256];
    int r = blockIdx.x;
    float4* row4 = (float4*)(out + (size_t)r * V);
    float mx = g_rowmax[r];
    float s = 0.f;
    for (int i = threadIdx.x; i < V / 4; i += 256) {
        float4 v = row4[i];
        s += expf(v.x - mx) + expf(v.y - mx) + expf(v.z - mx) + expf(v.w - mx);
    }
    red[threadIdx.x] = s;
    __syncthreads();
    for (int off = 128; off > 0; off >>= 1) {
        if (threadIdx.x < off) red[threadIdx.x] += red[threadIdx.x + off];
        __syncthreads();
    }
    float c = mx + logf(red[0]);
    for (int i = threadIdx.x; i < V / 4; i += 256) {
        float4 v = row4[i];
        v.x -= c; v.y -= c; v.z -= c; v.w -= c;
        row4[i] = v;
    }
}

// =====================================================================
// copy final hidden (buffer 0 after 64 steps) to output tail
// =====================================================================
__global__ void copy_h(float* __restrict__ dst)
{
    int b = blockIdx.x, k = threadIdx.x;
    dst[b * H + k] = g_h[0][k * B + b];
}

// =====================================================================
extern "C" void kernel_launch(void* const* d_in, const int* in_sizes, int n_in,
                              void* d_out, int out_size)
{
    const float* enc_h = (const float*)d_in[1];
    const float* emb   = (const float*)d_in[2];
    const float* Wih   = (const float*)d_in[3];
    const float* Whh   = (const float*)d_in[4];
    const float* bih   = (const float*)d_in[5];
    const float* bhh   = (const float*)d_in[6];
    const float* Wout  = (const float*)d_in[7];
    const float* bout  = (const float*)d_in[8];
    float* out = (float*)d_out;

    init_k<<<B, H>>>(enc_h);
    for (int t = 0; t < T; t++) {
        gru_gemm<<<dim3(48, KSP), 128>>>(Wih, Whh, emb, t);   // fused argmax(t-1)
        gru_cell<<<128, 256>>>(bih, bhh, t);
        logits_gemm<<<NMT, 128>>>(Wout, bout, out, t);
    }
    argmax_last<<<1, 1024>>>(T - 1);
    lsm_k<<<B * T, 256>>>(out);
    if ((long long)out_size >= OUT_LOGP + (long long)B * H)
        copy_h<<<B, H>>>(out + OUT_LOGP);
}